// round 13
// baseline (speedup 1.0000x reference)
#include <cuda_runtime.h>
#include <cuda_bf16.h>

// BWSGODE: 8192-step serial Euler recurrence on 4 scalars.
//
// Measured (R5 scalar non-contracted): 190.5us, rel_err 6.9e-10 vs 1e-3 ->
// dynamics are contractive; FMA-contraction drift is safe.
//
// Hot loop (mask==1 phase): 6x fma.rn.f32x2 + 2 scalar FADD + 1 off-chain
// scalar FMUL (W2=W*W from the previous iteration), down from 25 scalar FP
// ops. dW reassociated as tW*(W*W) (<=1 ulp/step, same class as contraction).
//
//  - mask phase-split: generic scalar loop while mask can be 0 (<= ~4 iters
//    for i~U[0,1)), then the specialized packed loop.
//  - trajectory staged in smem, one STS.128/iter (shared-space "r" address);
//    i-column filled by idle threads during the serial loop; coalesced
//    scatter afterwards.
//
// Held stable (bench starved seven rounds): the first successful measurement
// must attribute cleanly to the contraction+reassociation diff against R5.

#define NTHREADS 256

typedef unsigned long long u64;

#define FMA2(out, a, b, c) \
    asm("fma.rn.f32x2 %0, %1, %2, %3;" : "=l"(out) : "l"(a), "l"(b), "l"(c))

static __device__ __forceinline__ u64 pk(float lo, float hi) {
    u64 r;
    asm("mov.b64 %0, {%1, %2};" : "=l"(r) : "f"(lo), "f"(hi));
    return r;
}
static __device__ __forceinline__ void upk(u64 v, float& lo, float& hi) {
    asm("mov.b64 {%0, %1}, %2;" : "=f"(lo), "=f"(hi) : "l"(v));
}

__global__ __launch_bounds__(NTHREADS, 1)
void bwsg_ode_kernel(const float* __restrict__ y0,
                     const float* __restrict__ params,
                     float* __restrict__ out,
                     int nsteps) {
    extern __shared__ float buf[];  // nsteps * 4 floats (B,W,S,G per row)

    const int tid = threadIdx.x;
    const float i_val = y0[4];

    // Fill the i-column in parallel; overlaps with the serial loop below.
    for (int r = tid; r < nsteps; r += NTHREADS) {
        out[r * 5 + 4] = i_val;
    }

    if (tid == 0) {
        float B = y0[0];
        float W = y0[1];
        float S = y0[2];
        float G = y0[3];

        const float p0 = params[0], p1 = params[1], p2 = params[2],
                    p3 = params[3], p4 = params[4], p5 = params[5],
                    p6 = params[6], p7 = params[7], p8 = params[8],
                    p9 = params[9];

        const bool interventional = (i_val != 0.0f);
        const float thr = __fsub_rn(__fadd_rn(5.0f, i_val), 1.0f);

        // First step index at which mask is guaranteed 1 from then on.
        int s_start = 1;
        if (interventional) {
            float c = ceilf(thr);
            if (c < 1.0f) c = 1.0f;
            if (c > (float)nsteps) c = (float)nsteps;
            s_start = (int)c;
        }

        buf[0] = B; buf[1] = W; buf[2] = S; buf[3] = G;

        // ---- Phase 1: generic (mask computed per step), few iterations ----
        for (int s = 1; s < s_start; ++s) {
            const float j    = (float)s;
            const float ge   = (j >= thr) ? 1.0f : 0.0f;
            const float mask = interventional ? ge : 1.0f;

            const float omG = 1.0f - G;
            const float tG  = fmaf(p0, omG, -(p1 * S));
            const float dG  = tG * G;

            const float Bm = B * mask;

            const float uS = W + Bm;
            const float tS = fmaf(-p3, uS, fmaf(p2, G, -p4));
            const float dS = S * tS;

            const float tW = fmaf(-p6 * mask, B, fmaf(p5, S, -p7));
            const float dW = W * tW * W;

            const float uB = S + W;
            const float tB = fmaf(p8, uB, -p9);
            const float dB = Bm * tB;

            B += dB; W += dW; S += dS; G += dG;

            float* row = buf + s * 4;
            row[0] = B; row[1] = W; row[2] = S; row[3] = G;
        }

        // ---- Phase 2: mask == 1, packed FFMA2 hot loop ----
        // Lane layout: BW = (B lo, W hi), SG = (S lo, G hi).
        u64 BW = pk(B, W);
        u64 SG = pk(S, G);

        const u64 cA   = pk(p2, -p0);     // mul for (tS', tG')
        const u64 cC   = pk(-p4, p0);     // add: (p2*G - p4, p0 - p0*G)
        const u64 cN31 = pk(-p3, -p1);    // (tS, tG) = cN31*(uS,S) + t
        const u64 cP85 = pk(p8, p5);      // (tB', tW')
        const u64 cN97 = pk(-p9, -p7);
        const u64 cZN6 = pk(-0.0f, -p6);  // (tB, tW) = cZN6*(B,B) + t2

        // Off-chain: W^2 for the reassociated dW = tW*(W*W).
        float W2 = __fmul_rn(W, W);

        // 32-bit shared-space address for STS.128.
        unsigned rowp = (unsigned)__cvta_generic_to_shared(buf + s_start * 4);

        #pragma unroll 4
        for (int s = s_start; s < nsteps; ++s) {
            const float uS = W + B;       // W + B*mask, mask==1
            const float uB = S + W;

            // (tS, tG) = (p2*G - p3*uS - p4, p0*(1-G) - p1*S)
            u64 t;   FMA2(t, cA, pk(G, G), cC);
            u64 tSG; FMA2(tSG, cN31, pk(uS, S), t);
            // (S, G) += (S*tS, G*tG)
            u64 SGn; FMA2(SGn, tSG, SG, SG);

            // (tB, tW) = (p8*uB - p9, p5*S - p6*B - p7)
            u64 t2;  FMA2(t2, cP85, pk(uB, S), cN97);
            u64 tBW; FMA2(tBW, cZN6, pk(B, B), t2);
            // (B, W) += (tB*B, tW*W^2)
            u64 BWn; FMA2(BWn, tBW, pk(B, W2), BW);

            BW = BWn;
            SG = SGn;

            // One STS.128: row = {B, W, S, G} (little-endian lanes).
            asm volatile("st.shared.v2.u64 [%0], {%1, %2};"
                         :: "r"(rowp), "l"(BW), "l"(SG) : "memory");
            rowp += 16;

            upk(BW, B, W);
            upk(SG, S, G);
            W2 = __fmul_rn(W, W);         // off the packed critical path
        }
    }

    __syncthreads();

    // Coalesced scatter over the flat (nsteps,5) index space; col 4 was
    // already written during the serial loop.
    const int total = nsteps * 5;
    for (int idx = tid; idx < total; idx += NTHREADS) {
        const int r = idx / 5;
        const int c = idx - r * 5;
        if (c < 4) out[idx] = buf[r * 4 + c];
    }
}

extern "C" void kernel_launch(void* const* d_in, const int* in_sizes, int n_in,
                              void* d_out, int out_size) {
    const float* y0     = (const float*)d_in[0];
    const float* params = (const float*)d_in[1];
    float* out          = (float*)d_out;

    const int nsteps = out_size / 5;  // 8192
    const size_t smem = (size_t)nsteps * 4 * sizeof(float);  // 128 KB

    cudaFuncSetAttribute(bwsg_ode_kernel,
                         cudaFuncAttributeMaxDynamicSharedMemorySize,
                         (int)smem);

    bwsg_ode_kernel<<<1, NTHREADS, smem>>>(y0, params, out, nsteps);
}